// round 1
// baseline (speedup 1.0000x reference)
#include <cuda_runtime.h>

#define NBLOCKS 1184
#define NTHREADS 256

__device__ float g_partials[NBLOCKS];

__global__ __launch_bounds__(NTHREADS)
void qsum_reduce_kernel(const float* __restrict__ phi,
                        const float* __restrict__ w,
                        long long n4, long long n_total) {
    const float4* __restrict__ p4 = reinterpret_cast<const float4*>(phi);
    const float4* __restrict__ w4 = reinterpret_cast<const float4*>(w);

    float acc = 0.0f;
    long long tid    = (long long)blockIdx.x * NTHREADS + threadIdx.x;
    long long stride = (long long)gridDim.x * NTHREADS;

    // Main vectorized grid-stride loop: 2x float4 loads per iter (32B MLP/thread/iter)
    for (long long i = tid; i < n4; i += stride) {
        float4 a = p4[i];
        float4 b = w4[i];
        acc += __cosf(a.x * b.x);
        acc += __cosf(a.y * b.y);
        acc += __cosf(a.z * b.z);
        acc += __cosf(a.w * b.w);
    }

    // Scalar tail (n_total not multiple of 4) — first few threads only
    long long tail_base = n4 * 4;
    long long ti = tail_base + tid;
    if (ti < n_total) {
        acc += __cosf(phi[ti] * w[ti]);
    }

    // Warp reduce
    #pragma unroll
    for (int o = 16; o > 0; o >>= 1)
        acc += __shfl_xor_sync(0xffffffffu, acc, o);

    __shared__ float smem[NTHREADS / 32];
    if ((threadIdx.x & 31) == 0)
        smem[threadIdx.x >> 5] = acc;
    __syncthreads();

    // First warp reduces the (NTHREADS/32 = 8) warp partials
    if (threadIdx.x < 32) {
        float v = (threadIdx.x < NTHREADS / 32) ? smem[threadIdx.x] : 0.0f;
        #pragma unroll
        for (int o = 4; o > 0; o >>= 1)
            v += __shfl_xor_sync(0xffffffffu, v, o);
        if (threadIdx.x == 0)
            g_partials[blockIdx.x] = v;
    }
}

__global__ __launch_bounds__(NTHREADS)
void qsum_final_kernel(float* __restrict__ out, float bias, float inv_N) {
    float acc = 0.0f;
    for (int i = threadIdx.x; i < NBLOCKS; i += NTHREADS)
        acc += g_partials[i];

    #pragma unroll
    for (int o = 16; o > 0; o >>= 1)
        acc += __shfl_xor_sync(0xffffffffu, acc, o);

    __shared__ float smem[NTHREADS / 32];
    if ((threadIdx.x & 31) == 0)
        smem[threadIdx.x >> 5] = acc;
    __syncthreads();

    if (threadIdx.x < 32) {
        float v = (threadIdx.x < NTHREADS / 32) ? smem[threadIdx.x] : 0.0f;
        #pragma unroll
        for (int o = 4; o > 0; o >>= 1)
            v += __shfl_xor_sync(0xffffffffu, v, o);
        if (threadIdx.x == 0)
            out[0] = (v + bias) * inv_N;
    }
}

extern "C" void kernel_launch(void* const* d_in, const int* in_sizes, int n_in,
                              void* d_out, int out_size) {
    const float* phi = (const float*)d_in[0];
    const float* w   = (const float*)d_in[1];

    long long C = (long long)in_sizes[0];

    // N = 2^ceil(log2(C))
    int n = 0;
    while ((1LL << n) < C) n++;
    long long N = 1LL << n;

    float bias  = (float)(double)(N - C);
    float inv_N = (float)(1.0 / (double)N);

    long long n4 = C / 4;

    qsum_reduce_kernel<<<NBLOCKS, NTHREADS>>>(phi, w, n4, C);
    qsum_final_kernel<<<1, NTHREADS>>>((float*)d_out, bias, inv_N);
}

// round 2
// speedup vs baseline: 1.0007x; 1.0007x over previous
#include <cuda_runtime.h>

#define NBLOCKS 1184
#define NTHREADS 256

__device__ float        g_partials[NBLOCKS];
__device__ unsigned int g_counter = 0;   // self-resetting via atomicInc wrap

__global__ __launch_bounds__(NTHREADS)
void qsum_fused_kernel(const float* __restrict__ phi,
                       const float* __restrict__ w,
                       long long n4, long long n_total,
                       float bias, float inv_N,
                       float* __restrict__ out) {
    const float4* __restrict__ p4 = reinterpret_cast<const float4*>(phi);
    const float4* __restrict__ w4 = reinterpret_cast<const float4*>(w);

    float acc = 0.0f;
    long long tid    = (long long)blockIdx.x * NTHREADS + threadIdx.x;
    long long stride = (long long)gridDim.x * NTHREADS;

    // Main vectorized grid-stride loop: 2x LDG.128 per iter
    for (long long i = tid; i < n4; i += stride) {
        float4 a = p4[i];
        float4 b = w4[i];
        acc += __cosf(a.x * b.x);
        acc += __cosf(a.y * b.y);
        acc += __cosf(a.z * b.z);
        acc += __cosf(a.w * b.w);
    }

    // Scalar tail (n_total not multiple of 4)
    long long ti = n4 * 4 + tid;
    if (ti < n_total) {
        acc += __cosf(phi[ti] * w[ti]);
    }

    // Warp reduce
    #pragma unroll
    for (int o = 16; o > 0; o >>= 1)
        acc += __shfl_xor_sync(0xffffffffu, acc, o);

    __shared__ float smem[NTHREADS / 32];
    if ((threadIdx.x & 31) == 0)
        smem[threadIdx.x >> 5] = acc;
    __syncthreads();

    // Block partial -> global, then last block finishes
    __shared__ bool s_is_last;
    if (threadIdx.x == 0) {
        float v = 0.0f;
        #pragma unroll
        for (int i = 0; i < NTHREADS / 32; i++)
            v += smem[i];
        g_partials[blockIdx.x] = v;
        __threadfence();
        // atomicInc wraps to 0 when old == NBLOCKS-1 -> counter ready for next call
        unsigned int ticket = atomicInc(&g_counter, NBLOCKS - 1);
        s_is_last = (ticket == NBLOCKS - 1);
    }
    __syncthreads();

    if (s_is_last) {
        // Deterministic final reduction: fixed strided assignment + fixed tree
        float v = 0.0f;
        for (int i = threadIdx.x; i < NBLOCKS; i += NTHREADS)
            v += g_partials[i];

        #pragma unroll
        for (int o = 16; o > 0; o >>= 1)
            v += __shfl_xor_sync(0xffffffffu, v, o);

        if ((threadIdx.x & 31) == 0)
            smem[threadIdx.x >> 5] = v;
        __syncthreads();

        if (threadIdx.x < 32) {
            float t = (threadIdx.x < NTHREADS / 32) ? smem[threadIdx.x] : 0.0f;
            #pragma unroll
            for (int o = 4; o > 0; o >>= 1)
                t += __shfl_xor_sync(0xffffffffu, t, o);
            if (threadIdx.x == 0)
                out[0] = (t + bias) * inv_N;
        }
    }
}

extern "C" void kernel_launch(void* const* d_in, const int* in_sizes, int n_in,
                              void* d_out, int out_size) {
    const float* phi = (const float*)d_in[0];
    const float* w   = (const float*)d_in[1];

    long long C = (long long)in_sizes[0];

    // N = 2^ceil(log2(C))
    int n = 0;
    while ((1LL << n) < C) n++;
    long long N = 1LL << n;

    float bias  = (float)(double)(N - C);
    float inv_N = (float)(1.0 / (double)N);

    long long n4 = C / 4;

    qsum_fused_kernel<<<NBLOCKS, NTHREADS>>>(phi, w, n4, C, bias, inv_N,
                                             (float*)d_out);
}